// round 3
// baseline (speedup 1.0000x reference)
#include <cuda_runtime.h>

// ChamferLossSplit: B=256, N=M=256, D=4, PID_MAX=5.
// Inputs (metadata order): target f32 [B,N,4], reco f32 [B,M,4],
//                          in_pid i32 [B,N], out_pid i32 [B,M]
// Output: f32[2] = (mean per_nonzero, mean per_zero)

#define NPTS 256

__device__ __forceinline__ float warp_sum(float v) {
    #pragma unroll
    for (int o = 16; o; o >>= 1) v += __shfl_xor_sync(0xffffffffu, v, o);
    return v;
}

__global__ void chamfer_init(float* out) {
    out[0] = 0.0f;
    out[1] = 0.0f;
}

__global__ __launch_bounds__(NPTS) void chamfer_kernel(
    const float4* __restrict__ target,
    const float4* __restrict__ reco,
    const int* __restrict__ in_pid,
    const int* __restrict__ out_pid,
    float* __restrict__ out,
    float invB)
{
    __shared__ float4   s_r[NPTS];      // reco points for this batch
    __shared__ float    s_inv[NPTS];    // 0 if reco j valid, +inf if not
    __shared__ unsigned s_minyx[NPTS];  // min squared dist per reco j (uint bits)
    __shared__ float    s_red[6][8];    // cross-warp reduction buffer

    const int b = blockIdx.x;
    const int i = threadIdx.x;
    const float INF = __int_as_float(0x7f800000);

    const float4 t = target[b * NPTS + i];
    const float4 r = reco[b * NPTS + i];
    const int mx = (in_pid[b * NPTS + i] != 0);
    const int my = (out_pid[b * NPTS + i] != 0);

    s_r[i] = r;
    s_inv[i] = my ? 0.0f : INF;
    s_minyx[i] = 0x7f800000u;  // +inf bits
    __syncthreads();

    // Row mins (per target i) + column mins (per reco j) in one pass.
    float minxy = INF;  // min squared dist over valid j
    if (mx) {
        #pragma unroll 4
        for (int jj = 0; jj < NPTS; jj++) {
            const int j = (i + jj) & (NPTS - 1);
            const float4 rr = s_r[j];
            const float dx = t.x - rr.x;
            const float dy = t.y - rr.y;
            const float dz = t.z - rr.z;
            const float dw = t.w - rr.w;
            float d2 = dx * dx;
            d2 = fmaf(dy, dy, d2);
            d2 = fmaf(dz, dz, d2);
            d2 = fmaf(dw, dw, d2);
            // row min: only valid j count (s_inv pushes invalid to +inf)
            minxy = fminf(minxy, d2 + s_inv[j]);
            // column min: validity of j is applied later by the my-mask in
            // the sum, so raw d2 is fine here. Nonneg floats: uint order ==
            // float order. Pre-check makes the atomic rare after warm-up.
            const unsigned bits = __float_as_uint(d2);
            if (bits < s_minyx[j]) atomicMin(&s_minyx[j], bits);
        }
    }
    __syncthreads();

    const float minyx = __uint_as_float(s_minyx[i]);

    // Per-thread contributions (sqrt only here: 2 per thread, not 256)
    float v[6];
    v[0] = mx ? 1.0f : 0.0f;                                  // sum fx
    v[1] = my ? 1.0f : 0.0f;                                  // sum fy
    v[2] = mx ? sqrtf(minxy) : 0.0f;                          // sum_xy (may be inf if !has_y; gated below)
    v[3] = my ? sqrtf(minyx) : 0.0f;                          // sum_yx (may be inf if !has_x; gated below)
    {
        float tn = t.x * t.x;
        tn = fmaf(t.y, t.y, tn); tn = fmaf(t.z, t.z, tn); tn = fmaf(t.w, t.w, tn);
        v[4] = mx ? sqrtf(tn) : 0.0f;                         // fallback: sum ||x|| over valid x
        float rn = r.x * r.x;
        rn = fmaf(r.y, r.y, rn); rn = fmaf(r.z, r.z, rn); rn = fmaf(r.w, r.w, rn);
        v[5] = my ? 0.0f : sqrtf(rn);                         // sum ||y|| over zero-pid y
    }

    const int lane = i & 31;
    const int wid  = i >> 5;
    #pragma unroll
    for (int k = 0; k < 6; k++) {
        const float ws = warp_sum(v[k]);
        if (lane == 0) s_red[k][wid] = ws;
    }
    __syncthreads();

    if (i == 0) {
        float s[6];
        #pragma unroll
        for (int k = 0; k < 6; k++) {
            float acc = 0.0f;
            #pragma unroll
            for (int w = 0; w < 8; w++) acc += s_red[k][w];
            s[k] = acc;
        }
        const float sum_fx = s[0], sum_fy = s[1];
        const float sum_xy = s[2], sum_yx = s[3];
        const float sum_fb = s[4], sum_z  = s[5];

        const float n_in  = fmaxf(1.0f, sum_fx);
        const float n_out = fmaxf(1.0f, sum_fy);

        float per_nonzero;
        if (sum_fy == 0.0f) {
            per_nonzero = sum_fb / n_in;             // no valid reco
        } else if (sum_fx == 0.0f) {
            per_nonzero = 0.0f;                       // no valid target
        } else {
            per_nonzero = 0.5f * (sum_xy / n_out + sum_yx / n_in);
        }
        const float per_zero = sum_z / fmaxf(1.0f, (float)NPTS - sum_fy);

        atomicAdd(&out[0], per_nonzero * invB);
        atomicAdd(&out[1], per_zero * invB);
    }
}

extern "C" void kernel_launch(void* const* d_in, const int* in_sizes, int n_in,
                              void* d_out, int out_size)
{
    const float4* target  = (const float4*)d_in[0];
    const float4* reco    = (const float4*)d_in[1];
    const int*    in_pid  = (const int*)d_in[2];
    const int*    out_pid = (const int*)d_in[3];
    float*        out     = (float*)d_out;

    const int B = in_sizes[2] / NPTS;  // in_pid has B*N elements, N=256

    chamfer_init<<<1, 1>>>(out);
    chamfer_kernel<<<B, NPTS>>>(target, reco, in_pid, out_pid, out, 1.0f / (float)B);
}

// round 4
// speedup vs baseline: 1.3973x; 1.3973x over previous
#include <cuda_runtime.h>

// ChamferLossSplit: B=256, N=M=256, D=4, PID_MAX=5.
// Inputs: target f32 [B,N,4], reco f32 [B,M,4], in_pid i32 [B,N], out_pid i32 [B,M]
// Output: f32[2] = (mean per_nonzero, mean per_zero)

#define NPTS 256
#define NWARP 8
#define BIGC 1e18f   // sentinel coordinate for invalid points (BIGC^2*4 = 4e36, finite)

__device__ __forceinline__ float warp_sum(float v) {
    #pragma unroll
    for (int o = 16; o; o >>= 1) v += __shfl_xor_sync(0xffffffffu, v, o);
    return v;
}

__global__ void chamfer_init(float* out) {
    out[0] = 0.0f;
    out[1] = 0.0f;
}

__global__ __launch_bounds__(NPTS) void chamfer_kernel(
    const float4* __restrict__ target,
    const float4* __restrict__ reco,
    const int* __restrict__ in_pid,
    const int* __restrict__ out_pid,
    float* __restrict__ out,
    float invB)
{
    __shared__ float4   s_r[NPTS];              // reco pts (invalid -> BIGC coords)
    __shared__ float    s_rn[NPTS];             // |reco_j|^2 (of staged coords)
    __shared__ unsigned s_cmin[NWARP * NPTS];   // per-warp column-min slabs (uint bits)
    __shared__ float    s_red[6][NWARP];        // cross-warp reduction buffer

    const int b = blockIdx.x;
    const int i = threadIdx.x;
    const int lane = i & 31;
    const int wid  = i >> 5;
    const float INF = __int_as_float(0x7f800000);

    const float4 t0 = target[b * NPTS + i];
    const float4 r0 = reco[b * NPTS + i];
    const int mx = (in_pid[b * NPTS + i] != 0);
    const int my = (out_pid[b * NPTS + i] != 0);

    // Stage reco with validity folded into coordinates. Invalid points sit at
    // (BIGC,...) so every mixed valid/invalid pair has d2 ~ 4e36 and can never
    // win a min that survives masking. invalid x invalid cancels to ~0 but both
    // row (mx) and column (my) masks exclude those results.
    const float4 tv = mx ? t0 : make_float4(BIGC, BIGC, BIGC, BIGC);
    const float4 rv = my ? r0 : make_float4(BIGC, BIGC, BIGC, BIGC);
    {
        float rn = rv.x * rv.x;
        rn = fmaf(rv.y, rv.y, rn);
        rn = fmaf(rv.z, rv.z, rn);
        rn = fmaf(rv.w, rv.w, rn);
        s_r[i] = rv;
        s_rn[i] = rn;
    }
    __syncthreads();

    float tn = tv.x * tv.x;
    tn = fmaf(tv.y, tv.y, tn);
    tn = fmaf(tv.z, tv.z, tn);
    tn = fmaf(tv.w, tv.w, tn);

    // Main pass: broadcast reads (all lanes same j -> 1-phase LDS), dot-product
    // expansion d2 = tn + rn_j - 2*dot. Row min in a register; column min via
    // warp REDUX into this warp's smem slab (no atomics).
    float minxy = INF;
    #pragma unroll 8
    for (int j = 0; j < NPTS; j++) {
        const float4 rr = s_r[j];
        const float  rn = s_rn[j];
        float dot = tv.x * rr.x;
        dot = fmaf(tv.y, rr.y, dot);
        dot = fmaf(tv.z, rr.z, dot);
        dot = fmaf(tv.w, rr.w, dot);
        const float d2 = fmaf(-2.0f, dot, tn) + rn;
        minxy = fminf(minxy, d2);
        // clamp: dot expansion can round slightly negative; keep uint order valid
        const unsigned du = __float_as_uint(fmaxf(d2, 0.0f));
        const unsigned wm = __reduce_min_sync(0xffffffffu, du);
        if (lane == 0) s_cmin[wid * NPTS + j] = wm;
    }
    __syncthreads();

    // Combine the 8 per-warp slabs for column i.
    unsigned cm = s_cmin[i];
    #pragma unroll
    for (int w = 1; w < NWARP; w++) cm = min(cm, s_cmin[w * NPTS + i]);
    const float minyx = __uint_as_float(cm);

    // Per-thread contributions
    float v[6];
    v[0] = mx ? 1.0f : 0.0f;                               // sum fx
    v[1] = my ? 1.0f : 0.0f;                               // sum fy
    v[2] = mx ? sqrtf(fmaxf(minxy, 0.0f)) : 0.0f;          // sum_xy
    v[3] = my ? sqrtf(minyx) : 0.0f;                       // sum_yx
    {
        float a = t0.x * t0.x;
        a = fmaf(t0.y, t0.y, a); a = fmaf(t0.z, t0.z, a); a = fmaf(t0.w, t0.w, a);
        v[4] = mx ? sqrtf(a) : 0.0f;                       // fallback: sum ||x|| valid
        float c = r0.x * r0.x;
        c = fmaf(r0.y, r0.y, c); c = fmaf(r0.z, r0.z, c); c = fmaf(r0.w, r0.w, c);
        v[5] = my ? 0.0f : sqrtf(c);                       // sum ||y|| zero-pid
    }

    #pragma unroll
    for (int k = 0; k < 6; k++) {
        const float ws = warp_sum(v[k]);
        if (lane == 0) s_red[k][wid] = ws;
    }
    __syncthreads();

    if (i == 0) {
        float s[6];
        #pragma unroll
        for (int k = 0; k < 6; k++) {
            float acc = 0.0f;
            #pragma unroll
            for (int w = 0; w < NWARP; w++) acc += s_red[k][w];
            s[k] = acc;
        }
        const float sum_fx = s[0], sum_fy = s[1];
        const float sum_xy = s[2], sum_yx = s[3];
        const float sum_fb = s[4], sum_z  = s[5];

        const float n_in  = fmaxf(1.0f, sum_fx);
        const float n_out = fmaxf(1.0f, sum_fy);

        float per_nonzero;
        if (sum_fy == 0.0f) {
            per_nonzero = sum_fb / n_in;              // no valid reco
        } else if (sum_fx == 0.0f) {
            per_nonzero = 0.0f;                        // no valid target
        } else {
            per_nonzero = 0.5f * (sum_xy / n_out + sum_yx / n_in);
        }
        const float per_zero = sum_z / fmaxf(1.0f, (float)NPTS - sum_fy);

        atomicAdd(&out[0], per_nonzero * invB);
        atomicAdd(&out[1], per_zero * invB);
    }
}

extern "C" void kernel_launch(void* const* d_in, const int* in_sizes, int n_in,
                              void* d_out, int out_size)
{
    const float4* target  = (const float4*)d_in[0];
    const float4* reco    = (const float4*)d_in[1];
    const int*    in_pid  = (const int*)d_in[2];
    const int*    out_pid = (const int*)d_in[3];
    float*        out     = (float*)d_out;

    const int B = in_sizes[2] / NPTS;

    chamfer_init<<<1, 1>>>(out);
    chamfer_kernel<<<B, NPTS>>>(target, reco, in_pid, out_pid, out, 1.0f / (float)B);
}

// round 5
// speedup vs baseline: 2.0977x; 1.5013x over previous
#include <cuda_runtime.h>

// ChamferLossSplit: B=256, N=M=256, D=4, PID_MAX=5.
// Inputs: target f32 [B,N,4], reco f32 [B,M,4], in_pid i32 [B,N], out_pid i32 [B,M]
// Output: f32[2] = (mean per_nonzero, mean per_zero)
//
// Shuffle-ring scheme: each lane holds 8 target rows (rows lane+32k) so a warp
// holds all 256 rows. Each warp owns recos [32*wid, 32*wid+32); one reco per
// lane circulates through the warp via shfl, carrying its column-min with it.
// After 32 rotations each reco has met all 256 rows and its complete column
// min sits back on its home lane (column j == tid). Row mins are per-warp
// partial (over that warp's 32 recos) and combined once via smem slabs.

#define NPTS 256
#define NWARP 8
#define RPL 8          // rows per lane
#define BIGC 1e18f     // sentinel coord for invalid points (4*BIGC^2 finite)
#define FULLMASK 0xffffffffu

__device__ __forceinline__ float warp_sum(float v) {
    #pragma unroll
    for (int o = 16; o; o >>= 1) v += __shfl_xor_sync(FULLMASK, v, o);
    return v;
}

__global__ void chamfer_init(float* out) {
    out[0] = 0.0f;
    out[1] = 0.0f;
}

__global__ __launch_bounds__(NPTS) void chamfer_kernel(
    const float4* __restrict__ target,
    const float4* __restrict__ reco,
    const int* __restrict__ in_pid,
    const int* __restrict__ out_pid,
    float* __restrict__ out,
    float invB)
{
    __shared__ float s_row[NWARP * NPTS];   // per-warp partial row mins
    __shared__ float s_red[6][NWARP];       // cross-warp sum buffer

    const int b = blockIdx.x;
    const int i = threadIdx.x;
    const int lane = i & 31;
    const int wid  = i >> 5;
    const float INF = __int_as_float(0x7f800000);
    const int base = b * NPTS;

    // ---- own column j == i: load reco, mask, raw norm; stage validity ----
    const float4 r0 = reco[base + i];
    const int my = (out_pid[base + i] != 0);
    float rn0_raw;
    {
        float c = r0.x * r0.x;
        c = fmaf(r0.y, r0.y, c); c = fmaf(r0.z, r0.z, c); c = fmaf(r0.w, r0.w, c);
        rn0_raw = sqrtf(c);     // ||r0|| for zero-pid sum
    }
    float4 rr = my ? r0 : make_float4(BIGC, BIGC, BIGC, BIGC);
    float rn = rr.x * rr.x;
    rn = fmaf(rr.y, rr.y, rn); rn = fmaf(rr.z, rr.z, rn); rn = fmaf(rr.w, rr.w, rn);

    // ---- load 8 rows per lane (rows lane+32k); k==wid is this thread's own row i ----
    float4 tv[RPL];
    float tn[RPL], rm[RPL];
    int   mx_self = 0;
    float t0n_self = 0.0f;
    #pragma unroll
    for (int k = 0; k < RPL; k++) {
        const int row = lane + 32 * k;
        const float4 t0 = target[base + row];
        const int m = (in_pid[base + row] != 0);
        if (k == wid) {  // row == 32*wid + lane == i
            mx_self = m;
            float a = t0.x * t0.x;
            a = fmaf(t0.y, t0.y, a); a = fmaf(t0.z, t0.z, a); a = fmaf(t0.w, t0.w, a);
            t0n_self = sqrtf(a);    // ||t0|| for fallback sum
        }
        tv[k] = m ? t0 : make_float4(BIGC, BIGC, BIGC, BIGC);
        float a = tv[k].x * tv[k].x;
        a = fmaf(tv[k].y, tv[k].y, a);
        a = fmaf(tv[k].z, tv[k].z, a);
        a = fmaf(tv[k].w, tv[k].w, a);
        tn[k] = a;
        rm[k] = INF;
    }

    // ---- shuffle ring: 32 steps, reco + its column-min travel together ----
    float cmin = INF;
    const int src = (lane + 1) & 31;
    #pragma unroll 4
    for (int s = 0; s < 32; s++) {
        float d2[RPL];
        #pragma unroll
        for (int k = 0; k < RPL; k++) {
            float dot = tv[k].x * rr.x;
            dot = fmaf(tv[k].y, rr.y, dot);
            dot = fmaf(tv[k].z, rr.z, dot);
            dot = fmaf(tv[k].w, rr.w, dot);
            d2[k] = fmaf(-2.0f, dot, tn[k]) + rn;
            rm[k] = fminf(rm[k], d2[k]);
        }
        const float m0 = fminf(d2[0], d2[1]);
        const float m1 = fminf(d2[2], d2[3]);
        const float m2 = fminf(d2[4], d2[5]);
        const float m3 = fminf(d2[6], d2[7]);
        cmin = fminf(cmin, fminf(fminf(m0, m1), fminf(m2, m3)));
        rr.x = __shfl_sync(FULLMASK, rr.x, src);
        rr.y = __shfl_sync(FULLMASK, rr.y, src);
        rr.z = __shfl_sync(FULLMASK, rr.z, src);
        rr.w = __shfl_sync(FULLMASK, rr.w, src);
        rn   = __shfl_sync(FULLMASK, rn,   src);
        cmin = __shfl_sync(FULLMASK, cmin, src);
    }
    // cmin is now the full column min for column i.

    // ---- combine per-warp partial row mins via smem slabs ----
    #pragma unroll
    for (int k = 0; k < RPL; k++)
        s_row[wid * NPTS + lane + 32 * k] = rm[k];
    __syncthreads();

    float rowm = s_row[i];
    #pragma unroll
    for (int w = 1; w < NWARP; w++) rowm = fminf(rowm, s_row[w * NPTS + i]);

    // ---- per-thread contributions (sqrt clamped: dot-trick can round <0) ----
    float v[6];
    v[0] = mx_self ? 1.0f : 0.0f;                              // sum fx
    v[1] = my ? 1.0f : 0.0f;                                   // sum fy
    v[2] = mx_self ? sqrtf(fmaxf(rowm, 0.0f)) : 0.0f;          // sum_xy
    v[3] = my ? sqrtf(fmaxf(cmin, 0.0f)) : 0.0f;               // sum_yx
    v[4] = mx_self ? t0n_self : 0.0f;                          // fallback sum ||x||
    v[5] = my ? 0.0f : rn0_raw;                                // sum ||y|| zero-pid

    #pragma unroll
    for (int k = 0; k < 6; k++) {
        const float ws = warp_sum(v[k]);
        if (lane == 0) s_red[k][wid] = ws;
    }
    __syncthreads();

    if (i == 0) {
        float s[6];
        #pragma unroll
        for (int k = 0; k < 6; k++) {
            float acc = 0.0f;
            #pragma unroll
            for (int w = 0; w < NWARP; w++) acc += s_red[k][w];
            s[k] = acc;
        }
        const float sum_fx = s[0], sum_fy = s[1];
        const float sum_xy = s[2], sum_yx = s[3];
        const float sum_fb = s[4], sum_z  = s[5];

        const float n_in  = fmaxf(1.0f, sum_fx);
        const float n_out = fmaxf(1.0f, sum_fy);

        float per_nonzero;
        if (sum_fy == 0.0f) {
            per_nonzero = sum_fb / n_in;              // no valid reco
        } else if (sum_fx == 0.0f) {
            per_nonzero = 0.0f;                        // no valid target
        } else {
            per_nonzero = 0.5f * (sum_xy / n_out + sum_yx / n_in);
        }
        const float per_zero = sum_z / fmaxf(1.0f, (float)NPTS - sum_fy);

        atomicAdd(&out[0], per_nonzero * invB);
        atomicAdd(&out[1], per_zero * invB);
    }
}

extern "C" void kernel_launch(void* const* d_in, const int* in_sizes, int n_in,
                              void* d_out, int out_size)
{
    const float4* target  = (const float4*)d_in[0];
    const float4* reco    = (const float4*)d_in[1];
    const int*    in_pid  = (const int*)d_in[2];
    const int*    out_pid = (const int*)d_in[3];
    float*        out     = (float*)d_out;

    const int B = in_sizes[2] / NPTS;

    chamfer_init<<<1, 1>>>(out);
    chamfer_kernel<<<B, NPTS>>>(target, reco, in_pid, out_pid, out, 1.0f / (float)B);
}